// round 1
// baseline (speedup 1.0000x reference)
#include <cuda_runtime.h>
#include <math.h>
#include <stdint.h>

// Problem dims
#define BB   2048
#define DD   256
#define HH   512
#define NSLOT 64
#define FEAT 513
#define G4   2048   // 4*H

// Output layout offsets (float32 elements)
#define OFF_H      ((size_t)0)
#define OFF_C      ((size_t)1048576)
#define OFF_HMEM   ((size_t)2097152)
#define OFF_SLOTS  ((size_t)3145728)
#define OFF_CUM    ((size_t)36700160)
#define OFF_DELTA  ((size_t)70254592)
#define OFF_FILLED ((size_t)70385664)

// ------------------------------- scratch ------------------------------------
__device__ float g_q[BB * HH];
__device__ float g_kq[BB * DD];
__device__ float g_v[BB * DD];
__device__ int   g_idx[BB];
__device__ float g_bias[G4];
__device__ float g_mem[(size_t)NSLOT * BB * FEAT];   // mem_seq, layout [n][b][f]
__device__ float g_xg[(size_t)NSLOT * BB * G4];      // input projections [n][b][g]
__device__ float g_gates[(size_t)BB * G4];
__device__ float g_h[BB * HH];
__device__ float g_c[BB * HH];
__device__ int   g_fmode;                            // 0=f32,1=i32,2=u8,3=bf16

__device__ __forceinline__ float sigf(float x) { return 1.0f / (1.0f + expf(-x)); }

__device__ __forceinline__ int read_filled(const void* p, size_t i, int m) {
    if (m == 0) return ((const float*)p)[i] != 0.0f;
    if (m == 1) return ((const int*)p)[i] != 0;
    if (m == 2) return ((const unsigned char*)p)[i] != 0;
    return ((const unsigned short*)p)[i] != 0;   // bf16 bits
}

// ------------------------- dtype detection for `filled` ----------------------
__global__ void detect_filled_kernel(const unsigned int* __restrict__ w) {
    __shared__ int flags[3];  // [0]=saw 1.0f word, [1]=saw bf16 pair, [2]=saw other >1
    if (threadIdx.x < 3) flags[threadIdx.x] = 0;
    __syncthreads();
    // Smallest possible buffer: uint8 -> B*N bytes = 32768 words. Scan exactly that.
    for (int i = threadIdx.x; i < (BB * NSLOT) / 4; i += blockDim.x) {
        unsigned v = w[i];
        if (v == 0x3F800000u)      atomicOr(&flags[0], 1);
        else if (v == 0x3F803F80u) atomicOr(&flags[1], 1);
        else if (v > 1u)           atomicOr(&flags[2], 1);
    }
    __syncthreads();
    if (threadIdx.x == 0) {
        int m;
        if (flags[1])      m = 3;   // bf16 (pair 1,1 appears)
        else if (flags[0]) m = 0;   // float32
        else if (flags[2]) m = 2;   // packed uint8 bools
        else               m = 1;   // int32 (words only 0/1)
        g_fmode = m;
    }
}

// ------------------------------- small utils --------------------------------
__global__ void zero_hc_kernel() {
    int e = blockIdx.x * blockDim.x + threadIdx.x;
    if (e < BB * HH) { g_h[e] = 0.0f; g_c[e] = 0.0f; }
}

__global__ void combine_bias_kernel(const float* __restrict__ bih,
                                    const float* __restrict__ bhh) {
    int e = blockIdx.x * blockDim.x + threadIdx.x;
    if (e < G4) g_bias[e] = bih[e] + bhh[e];
}

// ------------------------------- SGEMM --------------------------------------
// C[m,n] = sum_k A[m,k] * W(n,k) [+ bias[n]] [+ Cin[m,n]]
// wTrans=1: W stored (N,K) row-major (i.e. A @ W.T) ; wTrans=0: W stored (K,N).
__global__ void __launch_bounds__(256)
sgemm_kernel(int M, int N, int K,
             const float* __restrict__ A, int lda,
             const float* __restrict__ W, int ldw, int wTrans,
             float* __restrict__ C, int ldc,
             const float* __restrict__ bias,
             const float* __restrict__ Cin) {
    __shared__ __align__(16) float As[16][128];
    __shared__ __align__(16) float Ws[16][128];

    const int tid = threadIdx.x;
    const int tx = tid & 15;         // 16 col-groups
    const int ty = tid >> 4;         // 16 row-groups
    const int bm = blockIdx.y * 128;
    const int bn = blockIdx.x * 128;

    float acc[8][8];
#pragma unroll
    for (int i = 0; i < 8; i++)
#pragma unroll
        for (int j = 0; j < 8; j++) acc[i][j] = 0.0f;

    for (int k0 = 0; k0 < K; k0 += 16) {
#pragma unroll
        for (int l = tid; l < 2048; l += 256) {
            int m = l >> 4, k = l & 15;
            int gm = bm + m, gk = k0 + k;
            As[k][m] = (gm < M && gk < K) ? A[(size_t)gm * lda + gk] : 0.0f;
        }
        if (wTrans) {
#pragma unroll
            for (int l = tid; l < 2048; l += 256) {
                int n = l >> 4, k = l & 15;
                int gn = bn + n, gk = k0 + k;
                Ws[k][n] = (gn < N && gk < K) ? W[(size_t)gn * ldw + gk] : 0.0f;
            }
        } else {
#pragma unroll
            for (int l = tid; l < 2048; l += 256) {
                int n = l >> 4, k = l & 15;
                int gn = bn + n, gk = k0 + k;
                Ws[k][n] = (gn < N && gk < K) ? W[(size_t)gk * ldw + gn] : 0.0f;
            }
        }
        __syncthreads();
#pragma unroll
        for (int k = 0; k < 16; k++) {
            float4 a0 = *(const float4*)&As[k][ty * 8];
            float4 a1 = *(const float4*)&As[k][ty * 8 + 4];
            float4 w0 = *(const float4*)&Ws[k][tx * 8];
            float4 w1 = *(const float4*)&Ws[k][tx * 8 + 4];
            float a[8] = {a0.x, a0.y, a0.z, a0.w, a1.x, a1.y, a1.z, a1.w};
            float w[8] = {w0.x, w0.y, w0.z, w0.w, w1.x, w1.y, w1.z, w1.w};
#pragma unroll
            for (int i = 0; i < 8; i++)
#pragma unroll
                for (int j = 0; j < 8; j++) acc[i][j] = fmaf(a[i], w[j], acc[i][j]);
        }
        __syncthreads();
    }

#pragma unroll
    for (int i = 0; i < 8; i++) {
        int gm = bm + ty * 8 + i;
        if (gm >= M) continue;
#pragma unroll
        for (int j = 0; j < 8; j++) {
            int gn = bn + tx * 8 + j;
            if (gn >= N) continue;
            float v = acc[i][j];
            if (bias) v += bias[gn];
            if (Cin) v += Cin[(size_t)gm * ldc + gn];
            C[(size_t)gm * ldc + gn] = v;
        }
    }
}

static inline void launch_sgemm(int M, int N, int K,
                                const float* A, int lda,
                                const float* W, int ldw, int wTrans,
                                float* C, int ldc,
                                const float* bias, const float* Cin) {
    dim3 grid((N + 127) / 128, (M + 127) / 128);
    sgemm_kernel<<<grid, 256>>>(M, N, K, A, lda, W, ldw, wTrans, C, ldc, bias, Cin);
}

// --------------------------- slot index selection ----------------------------
__global__ void select_idx_kernel(const float* __restrict__ slots,
                                  const void* __restrict__ filled) {
    const int b = blockIdx.x;
    const int t = threadIdx.x;  // 64 threads, one per slot
    __shared__ float kq_s[DD];
    __shared__ float sims[NSLOT];
    __shared__ int   emp[NSLOT];
    for (int d = t; d < DD; d += NSLOT) kq_s[d] = g_kq[b * DD + d];
    __syncthreads();
    const float* sp = slots + ((size_t)b * NSLOT + t) * DD;
    float s = 0.0f;
    for (int d = 0; d < DD; d++) s = fmaf(sp[d], kq_s[d], s);
    sims[t] = s;
    emp[t]  = !read_filled(filled, (size_t)b * NSLOT + t, g_fmode);
    __syncthreads();
    if (t == 0) {
        int idx = -1;
        for (int n = 0; n < NSLOT; n++) if (emp[n]) { idx = n; break; }
        if (idx < 0) {
            float best = sims[0]; idx = 0;
            for (int n = 1; n < NSLOT; n++) if (sims[n] > best) { best = sims[n]; idx = n; }
        }
        g_idx[b] = idx;
    }
}

// --------------------- slot update + output write + mem_seq ------------------
__global__ void update_write_kernel(const float* __restrict__ slots,
                                    const float* __restrict__ cum,
                                    const float* __restrict__ delta,
                                    const void* __restrict__ filled,
                                    const float* __restrict__ x,
                                    float* __restrict__ out) {
    size_t e = (size_t)blockIdx.x * blockDim.x + threadIdx.x;
    if (e >= (size_t)BB * NSLOT * DD) return;
    int d = (int)(e % DD);
    size_t bn = e / DD;
    int n = (int)(bn % NSLOT);
    int b = (int)(bn / NSLOT);
    int idx = g_idx[b];

    float xv = x[b * DD + d];
    float sl = slots[e];
    float cf = cum[e] + xv;
    if (n == idx) { sl = g_v[b * DD + d]; cf = xv; }

    out[OFF_SLOTS + e] = sl;
    out[OFF_CUM + e]   = cf;

    size_t mbase = ((size_t)n * BB + b) * FEAT;
    g_mem[mbase + d]      = sl;
    g_mem[mbase + DD + d] = cf;

    if (d == 0) {
        float dt = (n == idx) ? 0.0f : delta[bn] + 1.0f;
        out[OFF_DELTA + bn] = dt;
        g_mem[mbase + 2 * DD] = dt;
        int fl = (n == idx) ? 1 : read_filled(filled, bn, g_fmode);
        out[OFF_FILLED + bn] = fl ? 1.0f : 0.0f;
    }
}

// --------------------------- LSTM pointwise steps ---------------------------
__global__ void step_pointwise_kernel() {
    int e = blockIdx.x * blockDim.x + threadIdx.x;
    if (e >= BB * HH) return;
    int b = e / HH, j = e % HH;
    size_t base = (size_t)b * G4 + j;
    float i = sigf(g_gates[base]);
    float f = sigf(g_gates[base + HH]);
    float g = tanhf(g_gates[base + 2 * HH]);
    float o = sigf(g_gates[base + 3 * HH]);
    float c = f * g_c[e] + i * g;
    g_c[e] = c;
    g_h[e] = o * tanhf(c);
}

__global__ void outer_pointwise_kernel(const float* __restrict__ c_in,
                                       float* __restrict__ out) {
    int e = blockIdx.x * blockDim.x + threadIdx.x;
    if (e >= BB * HH) return;
    int b = e / HH, j = e % HH;
    size_t base = (size_t)b * G4 + j;
    float i = sigf(g_gates[base]);
    float f = sigf(g_gates[base + HH]);
    float g = tanhf(g_gates[base + 2 * HH]);
    float o = sigf(g_gates[base + 3 * HH]);
    float c = f * c_in[e] + i * g;
    out[OFF_C + e] = c;
    out[OFF_H + e] = o * tanhf(c);
    out[OFF_HMEM + e] = g_h[e];   // h_mem (final slot-LSTM hidden)
}

// --------------------------------- launch -----------------------------------
extern "C" void kernel_launch(void* const* d_in, const int* in_sizes, int n_in,
                              void* d_out, int out_size) {
    const float* x_t      = (const float*)d_in[0];
    const float* h_lstm   = (const float*)d_in[1];
    const float* c_lstm   = (const float*)d_in[2];
    // d_in[3] = h_mem_prev: unused by the reference
    const float* slots    = (const float*)d_in[4];
    const float* cum      = (const float*)d_in[5];
    const float* delta    = (const float*)d_in[6];
    const void*  filled   = (const void*)d_in[7];
    const float* Wq       = (const float*)d_in[8];
    const float* Wk       = (const float*)d_in[9];
    const float* Wv       = (const float*)d_in[10];
    const float* bv       = (const float*)d_in[11];
    const float* lstm_Wih = (const float*)d_in[12];
    const float* lstm_Whh = (const float*)d_in[13];
    const float* lstm_bih = (const float*)d_in[14];
    const float* lstm_bhh = (const float*)d_in[15];
    const float* W_ih     = (const float*)d_in[16];
    const float* b_ih     = (const float*)d_in[17];
    const float* W_hh     = (const float*)d_in[18];
    float* out = (float*)d_out;

    // Resolve scratch addresses
    float *p_q, *p_kq, *p_v, *p_mem, *p_xg, *p_gates, *p_h, *p_c, *p_bias;
    cudaGetSymbolAddress((void**)&p_q, g_q);
    cudaGetSymbolAddress((void**)&p_kq, g_kq);
    cudaGetSymbolAddress((void**)&p_v, g_v);
    cudaGetSymbolAddress((void**)&p_mem, g_mem);
    cudaGetSymbolAddress((void**)&p_xg, g_xg);
    cudaGetSymbolAddress((void**)&p_gates, g_gates);
    cudaGetSymbolAddress((void**)&p_h, g_h);
    cudaGetSymbolAddress((void**)&p_c, g_c);
    cudaGetSymbolAddress((void**)&p_bias, g_bias);

    // 0) detect `filled` dtype, init recurrent state, combined slot-LSTM bias
    detect_filled_kernel<<<1, 256>>>((const unsigned int*)filled);
    zero_hc_kernel<<<(BB * HH + 255) / 256, 256>>>();
    combine_bias_kernel<<<(G4 + 255) / 256, 256>>>(lstm_bih, lstm_bhh);

    // 1) q = x @ Wq.T ; kq = q @ Wk ; v = x @ Wv.T + bv
    launch_sgemm(BB, HH, DD, x_t, DD, Wq, DD, 1, p_q, HH, nullptr, nullptr);
    launch_sgemm(BB, DD, HH, p_q, HH, Wk, DD, 0, p_kq, DD, nullptr, nullptr);
    launch_sgemm(BB, DD, DD, x_t, DD, Wv, DD, 1, p_v, DD, bv, nullptr);

    // 2) slot index selection (first-empty else argmax sims)
    select_idx_kernel<<<BB, NSLOT>>>(slots, filled);

    // 3) slot/cum/delta/filled update -> outputs + mem_seq [n][b][f]
    {
        size_t tot = (size_t)BB * NSLOT * DD;
        update_write_kernel<<<(unsigned)((tot + 255) / 256), 256>>>(
            slots, cum, delta, filled, x_t, out);
    }

    // 4) xg[n,b,:] = mem_seq[n,b,:] @ Wih.T + (bih+bhh)   (M=131072,N=2048,K=513)
    launch_sgemm(NSLOT * BB, G4, FEAT, p_mem, FEAT, lstm_Wih, FEAT, 1,
                 p_xg, G4, p_bias, nullptr);

    // 5) recurrence over 64 slots
    for (int n = 0; n < NSLOT; n++) {
        const float* xg_n = p_xg + (size_t)n * BB * G4;
        launch_sgemm(BB, G4, HH, p_h, HH, lstm_Whh, HH, 1,
                     p_gates, G4, nullptr, xg_n);
        step_pointwise_kernel<<<(BB * HH + 255) / 256, 256>>>();
    }

    // 6) outer LSTM: gates = x@Wih_x.T + b_ih + h_mem@Wih_h.T + h_lstm@W_hh.T
    launch_sgemm(BB, G4, DD, x_t, DD, W_ih, DD + HH, 1, p_gates, G4, b_ih, nullptr);
    launch_sgemm(BB, G4, HH, p_h, HH, W_ih + DD, DD + HH, 1, p_gates, G4, nullptr, p_gates);
    launch_sgemm(BB, G4, HH, h_lstm, HH, W_hh, HH, 1, p_gates, G4, nullptr, p_gates);
    outer_pointwise_kernel<<<(BB * HH + 255) / 256, 256>>>(c_lstm, out);
}